// round 9
// baseline (speedup 1.0000x reference)
#include <cuda_runtime.h>
#include <cuda_fp16.h>
#include <cuda_bf16.h>

#define N_NODES 1200000
#define E_EDGES 12000000
#define D_IN    10
#define D_H     20
#define D_ENC   5
#define VEC     6
#define B_ROWS  200000
#define NB_SCAN ((N_NODES + 1023) / 1024)   // 1172

// ---- scratch (device globals; allocation-free) ----
__device__ int    g_cnt [N_NODES];          // degree histogram
__device__ int    g_off [N_NODES + 1];      // CSR offsets (exclusive scan)
__device__ int    g_cur [N_NODES];          // atomic cursors for position scatter
__device__ int    g_blk [NB_SCAN];          // per-block sums for scan
__device__ int    g_csr [E_EDGES];          // src ids sorted by dst
__device__ float  g_dinv[N_NODES];
// layer-1 gather source: h*dinv, fp16, tight 20-half rows (40B, 8B-aligned)
__device__ __half g_h1  [N_NODES * 20];
// layer-2 gather source: h2*dinv, fp16, 8-half rows (16B, halfs 5-7 zero)
__device__ __half g_h2  [N_NODES * 8];
// layer-2 aggregate, fp16, 8-half rows
__device__ __half g_acc2[N_NODES * 8];

__device__ __forceinline__ float gelu_exact(float v) { return v * normcdff(v); }

// ---------------------------------------------------------------- build CSR

__global__ void k_zero_cnt() {
    int i = blockIdx.x * blockDim.x + threadIdx.x;
    if (i < N_NODES) g_cnt[i] = 0;
}

__global__ void k_hist(const int* __restrict__ ei) {
    int e = blockIdx.x * blockDim.x + threadIdx.x;
    if (e < E_EDGES) atomicAdd(&g_cnt[__ldcs(ei + E_EDGES + e)], 1);
}

// scan A: per-1024-chunk exclusive scan (256 thr x 4 elems), block sums to g_blk
__global__ void k_scanA() {
    __shared__ int wsum[8];
    int blk = blockIdx.x;
    int base = blk * 1024 + threadIdx.x * 4;
    int v[4];
#pragma unroll
    for (int q = 0; q < 4; q++) {
        int idx = base + q;
        v[q] = (idx < N_NODES) ? g_cnt[idx] : 0;
    }
    int tsum = v[0] + v[1] + v[2] + v[3];
    int lane = threadIdx.x & 31, wid = threadIdx.x >> 5;
    int inc = tsum;
#pragma unroll
    for (int d = 1; d < 32; d <<= 1) {
        int n = __shfl_up_sync(0xFFFFFFFFu, inc, d);
        if (lane >= d) inc += n;
    }
    if (lane == 31) wsum[wid] = inc;
    __syncthreads();
    if (threadIdx.x == 0) {
        int run = 0;
#pragma unroll
        for (int w = 0; w < 8; w++) { int t = wsum[w]; wsum[w] = run; run += t; }
        g_blk[blk] = run;
    }
    __syncthreads();
    int excl = wsum[wid] + inc - tsum;
    int run = excl;
#pragma unroll
    for (int q = 0; q < 4; q++) {
        int idx = base + q;
        if (idx < N_NODES) g_off[idx] = run;
        run += v[q];
    }
}

// scan B: one 1024-thread block scans the NB_SCAN block sums (2 elems/thread)
__global__ void k_scanB() {
    __shared__ int wsum[32];
    int t = threadIdx.x;
    int v0 = (2*t   < NB_SCAN) ? g_blk[2*t]   : 0;
    int v1 = (2*t+1 < NB_SCAN) ? g_blk[2*t+1] : 0;
    int tsum = v0 + v1;
    int lane = t & 31, wid = t >> 5;
    int inc = tsum;
#pragma unroll
    for (int d = 1; d < 32; d <<= 1) {
        int n = __shfl_up_sync(0xFFFFFFFFu, inc, d);
        if (lane >= d) inc += n;
    }
    if (lane == 31) wsum[wid] = inc;
    __syncthreads();
    if (t == 0) {
        int run = 0;
#pragma unroll
        for (int w = 0; w < 32; w++) { int s = wsum[w]; wsum[w] = run; run += s; }
    }
    __syncthreads();
    int excl = wsum[wid] + inc - tsum;
    if (2*t   < NB_SCAN) g_blk[2*t]   = excl;
    if (2*t+1 < NB_SCAN) g_blk[2*t+1] = excl + v0;
}

// scan C: add block offsets, produce final g_off and cursor copy g_cur
__global__ void k_scanC() {
    int i = blockIdx.x * blockDim.x + threadIdx.x;
    if (i < N_NODES) {
        int v = g_off[i] + g_blk[i >> 10];
        g_off[i] = v;
        g_cur[i] = v;
    }
    if (i == 0) g_off[N_NODES] = E_EDGES;
}

// position scatter: csr[pos++] = src, bucketed by dst
__global__ void k_pos(const int* __restrict__ ei) {
    int e = blockIdx.x * blockDim.x + threadIdx.x;
    if (e >= E_EDGES) return;
    int s = __ldcs(ei + e);
    int d = __ldcs(ei + E_EDGES + e);
    int p = atomicAdd(&g_cur[d], 1);
    g_csr[p] = s;
}

// ---------------------------------------------------------------- GNN

// dinv; h = (x+po)@W1 * dinv ; write fp16 gather rows
__global__ void k_node1(const float* __restrict__ x, const float* __restrict__ W1) {
    __shared__ float sW[D_IN * D_H];
    if (threadIdx.x < D_IN * D_H) sW[threadIdx.x] = W1[threadIdx.x];
    __syncthreads();

    int i = blockIdx.x * blockDim.x + threadIdx.x;
    if (i >= N_NODES) return;

    float dinv = rsqrtf((float)g_cnt[i] + 1.0f);
    g_dinv[i] = dinv;

    float xi[D_IN];
#pragma unroll
    for (int j = 0; j < D_IN; j++) xi[j] = x[(size_t)i * D_IN + j] + sinf((float)j);

    float h[D_H];
#pragma unroll
    for (int k = 0; k < D_H; k++) {
        float s = 0.0f;
#pragma unroll
        for (int j = 0; j < D_IN; j++) s = fmaf(xi[j], sW[j * D_H + k], s);
        h[k] = s * dinv;
    }

    __half hv[20];
#pragma unroll
    for (int k = 0; k < D_H; k++) hv[k] = __float2half_rn(h[k]);
    __half* hp = &g_h1[(size_t)i * 20];
    const uint2* src2 = reinterpret_cast<const uint2*>(hv);
#pragma unroll
    for (int q = 0; q < 5; q++) reinterpret_cast<uint2*>(hp)[q] = src2[q];
}

// fused layer-1 aggregate + node transform. 8 lanes cooperate per node.
__global__ void k_gather1(const float* __restrict__ b1, const float* __restrict__ W2) {
    __shared__ float sW[D_H * D_ENC];
    __shared__ float sb[D_H];
    if (threadIdx.x < D_H * D_ENC) sW[threadIdx.x] = W2[threadIdx.x];
    if (threadIdx.x < D_H) sb[threadIdx.x] = b1[threadIdx.x];
    __syncthreads();

    int gid = blockIdx.x * blockDim.x + threadIdx.x;
    int i = gid >> 3;             // node
    int l8 = gid & 7;             // lane within octet
    if (i >= N_NODES) return;

    float acc[D_H];
#pragma unroll
    for (int k = 0; k < D_H; k++) acc[k] = 0.0f;

    if (l8 == 0) {                // self term once
        const __half* hp = &g_h1[(size_t)i * 20];
        uint2 a[5];
#pragma unroll
        for (int q = 0; q < 5; q++) a[q] = reinterpret_cast<const uint2*>(hp)[q];
        const __half2* h2v = reinterpret_cast<const __half2*>(a);
#pragma unroll
        for (int k = 0; k < 10; k++) {
            float2 f = __half22float2(h2v[k]);
            acc[2*k] += f.x; acc[2*k+1] += f.y;
        }
    }

    int beg = g_off[i], end = g_off[i + 1];
    for (int e = beg + l8; e < end; e += 8) {
        int s = g_csr[e];
        const __half* hp = &g_h1[(size_t)s * 20];
        uint2 a[5];
#pragma unroll
        for (int q = 0; q < 5; q++) a[q] = reinterpret_cast<const uint2*>(hp)[q];
        const __half2* h2v = reinterpret_cast<const __half2*>(a);
#pragma unroll
        for (int k = 0; k < 10; k++) {
            float2 f = __half22float2(h2v[k]);
            acc[2*k] += f.x; acc[2*k+1] += f.y;
        }
    }

    // octet butterfly reduce -> lane 0 holds full sum
#pragma unroll
    for (int k = 0; k < D_H; k++) {
        acc[k] += __shfl_xor_sync(0xFFFFFFFFu, acc[k], 1);
        acc[k] += __shfl_xor_sync(0xFFFFFFFFu, acc[k], 2);
        acc[k] += __shfl_xor_sync(0xFFFFFFFFu, acc[k], 4);
    }

    if (l8 != 0) return;

    float dinv = g_dinv[i];
    float h1[D_H];
#pragma unroll
    for (int k = 0; k < D_H; k++)
        h1[k] = gelu_exact(fmaf(dinv, acc[k], sb[k]));

    float h2[D_ENC];
#pragma unroll
    for (int c = 0; c < D_ENC; c++) {
        float s = 0.0f;
#pragma unroll
        for (int k = 0; k < D_H; k++) s = fmaf(h1[k], sW[k * D_ENC + c], s);
        h2[c] = s * dinv;
    }

    __half hv[8];
#pragma unroll
    for (int k = 0; k < D_ENC; k++) hv[k] = __float2half_rn(h2[k]);
#pragma unroll
    for (int k = D_ENC; k < 8; k++) hv[k] = __float2half_rn(0.f);
    *reinterpret_cast<uint4*>(&g_h2[(size_t)i * 8]) = *reinterpret_cast<const uint4*>(hv);
}

// layer-2 aggregate. 4 lanes cooperate per node.
__global__ void k_gather2() {
    int gid = blockIdx.x * blockDim.x + threadIdx.x;
    int i = gid >> 2;
    int l4 = gid & 3;
    if (i >= N_NODES) return;

    float acc[6] = {0.f, 0.f, 0.f, 0.f, 0.f, 0.f};

    if (l4 == 0) {
        uint4 w = *reinterpret_cast<const uint4*>(&g_h2[(size_t)i * 8]);
        const __half2* h2v = reinterpret_cast<const __half2*>(&w);
#pragma unroll
        for (int k = 0; k < 3; k++) {
            float2 f = __half22float2(h2v[k]);
            acc[2*k] += f.x; acc[2*k+1] += f.y;
        }
    }

    int beg = g_off[i], end = g_off[i + 1];
    for (int e = beg + l4; e < end; e += 4) {
        int s = g_csr[e];
        uint4 w = *reinterpret_cast<const uint4*>(&g_h2[(size_t)s * 8]);
        const __half2* h2v = reinterpret_cast<const __half2*>(&w);
#pragma unroll
        for (int k = 0; k < 3; k++) {
            float2 f = __half22float2(h2v[k]);
            acc[2*k] += f.x; acc[2*k+1] += f.y;
        }
    }

#pragma unroll
    for (int k = 0; k < 6; k++) {
        acc[k] += __shfl_xor_sync(0xFFFFFFFFu, acc[k], 1);
        acc[k] += __shfl_xor_sync(0xFFFFFFFFu, acc[k], 2);
    }

    if (l4 != 0) return;

    __half hv[8];
#pragma unroll
    for (int k = 0; k < 6; k++) hv[k] = __float2half_rn(acc[k]);
    hv[6] = __float2half_rn(0.f); hv[7] = __float2half_rn(0.f);
    *reinterpret_cast<uint4*>(&g_acc2[(size_t)i * 8]) = *reinterpret_cast<const uint4*>(hv);
}

// epilogue
__global__ void k_final(const float* __restrict__ b2,
                        const float* __restrict__ We, const float* __restrict__ be,
                        const float* __restrict__ Wd, const float* __restrict__ bd,
                        const float* __restrict__ Wr, const float* __restrict__ br,
                        float* __restrict__ out) {
    __shared__ float sWe[30 * 30];
    __shared__ float sWd[30 * 60];
    __shared__ float sWr[30 * 7];
    __shared__ float sbe[30], sbd[60], sbr[7], sb2[5];

    for (int t = threadIdx.x; t < 900;  t += blockDim.x) sWe[t] = We[t];
    for (int t = threadIdx.x; t < 1800; t += blockDim.x) sWd[t] = Wd[t];
    for (int t = threadIdx.x; t < 210;  t += blockDim.x) sWr[t] = Wr[t];
    if (threadIdx.x < 30) sbe[threadIdx.x] = be[threadIdx.x];
    if (threadIdx.x < 60) sbd[threadIdx.x] = bd[threadIdx.x];
    if (threadIdx.x < 7)  sbr[threadIdx.x] = br[threadIdx.x];
    if (threadIdx.x < 5)  sb2[threadIdx.x] = b2[threadIdx.x];
    __syncthreads();

    int b = blockIdx.x * blockDim.x + threadIdx.x;
    if (b >= B_ROWS) return;

    float r[30];
#pragma unroll
    for (int v = 0; v < VEC; v++) {
        int node = b * VEC + v;
        float dinv = g_dinv[node];
        uint4 w = *reinterpret_cast<const uint4*>(&g_acc2[(size_t)node * 8]);
        const __half* hv = reinterpret_cast<const __half*>(&w);
#pragma unroll
        for (int k = 0; k < D_ENC; k++)
            r[v * D_ENC + k] = gelu_exact(fmaf(dinv, __half2float(hv[k]), sb2[k]));
    }

    float enc[30];
#pragma unroll
    for (int o = 0; o < 30; o++) {
        float s = sbe[o];
#pragma unroll
        for (int j = 0; j < 30; j++) s = fmaf(r[j], sWe[j * 30 + o], s);
        enc[o] = s;
    }

    float* px1 = out + (size_t)b * 7;
#pragma unroll
    for (int o = 0; o < 7; o++) {
        float s = sbr[o];
#pragma unroll
        for (int j = 0; j < 30; j++) s = fmaf(enc[j], sWr[j * 7 + o], s);
        px1[o] = s;
    }

    float* pe = out + (size_t)B_ROWS * 7 + (size_t)b * 30;
#pragma unroll
    for (int o = 0; o < 30; o++) pe[o] = enc[o];

#pragma unroll
    for (int j = 0; j < 30; j++) r[j] = gelu_exact(enc[j]);
    float* po = out + (size_t)B_ROWS * 37 + (size_t)b * 60;
#pragma unroll
    for (int o = 0; o < 60; o++) {
        float s = sbd[o];
#pragma unroll
        for (int j = 0; j < 30; j++) s = fmaf(r[j], sWd[j * 60 + o], s);
        po[o] = s;
    }
}

// ---------------------------------------------------------------- launch

extern "C" void kernel_launch(void* const* d_in, const int* in_sizes, int n_in,
                              void* d_out, int out_size) {
    const float* x  = (const float*)d_in[0];
    const int*   ei = (const int*)  d_in[1];
    const float* W1 = (const float*)d_in[2];
    const float* b1 = (const float*)d_in[3];
    const float* W2 = (const float*)d_in[4];
    const float* b2 = (const float*)d_in[5];
    const float* We = (const float*)d_in[6];
    const float* be = (const float*)d_in[7];
    const float* Wd = (const float*)d_in[8];
    const float* bd = (const float*)d_in[9];
    const float* Wr = (const float*)d_in[10];
    const float* br = (const float*)d_in[11];
    float* out = (float*)d_out;

    const int TB = 256;
    int gN  = (N_NODES + TB - 1) / TB;
    int gE  = (E_EDGES + TB - 1) / TB;
    int gB  = (B_ROWS + TB - 1) / TB;
    int gN8 = (int)(((long long)N_NODES * 8 + TB - 1) / TB);
    int gN4 = (int)(((long long)N_NODES * 4 + TB - 1) / TB);

    k_zero_cnt<<<gN, TB>>>();
    k_hist<<<gE, TB>>>(ei);
    k_scanA<<<NB_SCAN, 256>>>();
    k_scanB<<<1, 1024>>>();
    k_scanC<<<gN, TB>>>();
    k_pos<<<gE, TB>>>(ei);
    k_node1<<<gN, TB>>>(x, W1);
    k_gather1<<<gN8, TB>>>(b1, W2);
    k_gather2<<<gN4, TB>>>();
    k_final<<<gB, TB>>>(b2, We, be, Wd, bd, Wr, br, out);
}

// round 10
// speedup vs baseline: 1.3917x; 1.3917x over previous
#include <cuda_runtime.h>
#include <cuda_fp16.h>
#include <cuda_bf16.h>

#define N_NODES 1200000
#define E_EDGES 12000000
#define D_IN    10
#define D_H     20
#define D_ENC   5
#define VEC     6
#define B_ROWS  200000

// ---- scratch (device globals; allocation-free) ----
__device__ float  g_deg [N_NODES];
__device__ float  g_dinv[N_NODES];
// layer-1 gather source: h*dinv, fp16, tight 20-half rows (40B, 8B-aligned)
__device__ __half g_h1  [N_NODES * 20];
// layer-1 accumulator: fp16, 24-half rows (48B, 16B-aligned for red.v4.f16x2)
__device__ __half g_acc1[N_NODES * 24];
// layer-2 gather source: h2*dinv, fp16, 8-half rows (16B, halfs 5-7 zero)
__device__ __half g_h2  [N_NODES * 8];
// layer-2 accumulator: fp16, 8-half rows (16B) -> one v4 RED
__device__ __half g_acc2[N_NODES * 8];

__device__ __forceinline__ float gelu_exact(float v) { return v * normcdff(v); }

__device__ __forceinline__ void red_add_v4h2(__half* p, unsigned a, unsigned b,
                                             unsigned c, unsigned d) {
    asm volatile("red.global.add.noftz.v4.f16x2 [%0], {%1,%2,%3,%4};"
                 :: "l"(p), "r"(a), "r"(b), "r"(c), "r"(d) : "memory");
}
__device__ __forceinline__ void red_add_v2h2(__half* p, unsigned a, unsigned b) {
    asm volatile("red.global.add.noftz.v2.f16x2 [%0], {%1,%2};"
                 :: "l"(p), "r"(a), "r"(b) : "memory");
}

// ---------------------------------------------------------------- kernels

// degree histogram: 4 edges per thread via one int4 streaming load
__global__ void k_deg4(const int* __restrict__ ei) {
    int t = blockIdx.x * blockDim.x + threadIdx.x;
    int base = t * 4;
    if (base + 3 < E_EDGES) {
        int4 d4 = __ldcs(reinterpret_cast<const int4*>(ei + E_EDGES + base));
        atomicAdd(&g_deg[d4.x], 1.0f);
        atomicAdd(&g_deg[d4.y], 1.0f);
        atomicAdd(&g_deg[d4.z], 1.0f);
        atomicAdd(&g_deg[d4.w], 1.0f);
    } else {
        for (int e = base; e < E_EDGES; e++)
            atomicAdd(&g_deg[__ldcs(ei + E_EDGES + e)], 1.0f);
    }
}

// dinv; h = (x+po)@W1 * dinv ; write fp16 gather row + fp16 acc init (self term)
__global__ void k_node1(const float* __restrict__ x, const float* __restrict__ W1) {
    __shared__ float sW[D_IN * D_H];
    if (threadIdx.x < D_IN * D_H) sW[threadIdx.x] = W1[threadIdx.x];
    __syncthreads();

    int i = blockIdx.x * blockDim.x + threadIdx.x;
    if (i >= N_NODES) return;

    float dinv = rsqrtf(g_deg[i] + 1.0f);
    g_dinv[i] = dinv;

    float xi[D_IN];
#pragma unroll
    for (int j = 0; j < D_IN; j++) xi[j] = __ldcs(x + (size_t)i * D_IN + j) + sinf((float)j);

    float h[D_H];
#pragma unroll
    for (int k = 0; k < D_H; k++) {
        float s = 0.0f;
#pragma unroll
        for (int j = 0; j < D_IN; j++) s = fmaf(xi[j], sW[j * D_H + k], s);
        h[k] = s * dinv;   // pre-scaled by source dinv
    }

    __half hv[24];
#pragma unroll
    for (int k = 0; k < D_H; k++) hv[k] = __float2half_rn(h[k]);
#pragma unroll
    for (int k = D_H; k < 24; k++) hv[k] = __float2half_rn(0.f);

    // gather source: tight 40B row, 8B-aligned -> 5x uint2
    __half* hp = &g_h1[(size_t)i * 20];
    const uint2* src2 = reinterpret_cast<const uint2*>(hv);
#pragma unroll
    for (int q = 0; q < 5; q++) reinterpret_cast<uint2*>(hp)[q] = src2[q];

    // accumulator init: 48B row, 16B-aligned -> 3x uint4
    __half* ap = &g_acc1[(size_t)i * 24];
    const uint4* src4 = reinterpret_cast<const uint4*>(hv);
#pragma unroll
    for (int q = 0; q < 3; q++) reinterpret_cast<uint4*>(ap)[q] = src4[q];
}

// layer-1 edge scatter: gather -> 3 fp16 REDs (v4+v4+v2)
__global__ void k_edge1(const int* __restrict__ ei) {
    int e = blockIdx.x * blockDim.x + threadIdx.x;
    if (e >= E_EDGES) return;
    int s = __ldcs(ei + e);
    int d = __ldcs(ei + E_EDGES + e);

    const __half* hp = &g_h1[(size_t)s * 20];
    uint2 a0 = reinterpret_cast<const uint2*>(hp)[0];
    uint2 a1 = reinterpret_cast<const uint2*>(hp)[1];
    uint2 a2 = reinterpret_cast<const uint2*>(hp)[2];
    uint2 a3 = reinterpret_cast<const uint2*>(hp)[3];
    uint2 a4 = reinterpret_cast<const uint2*>(hp)[4];

    __half* ad = &g_acc1[(size_t)d * 24];
    red_add_v4h2(ad,      a0.x, a0.y, a1.x, a1.y);
    red_add_v4h2(ad + 8,  a2.x, a2.y, a3.x, a3.y);
    red_add_v2h2(ad + 16, a4.x, a4.y);
}

// h1 = gelu(dinv*acc1 + b1); h2 = (h1@W2)*dinv ; write fp16 h2 + fp16 acc2 init
__global__ void k_node2(const float* __restrict__ b1, const float* __restrict__ W2) {
    __shared__ float sW[D_H * D_ENC];
    __shared__ float sb[D_H];
    if (threadIdx.x < D_H * D_ENC) sW[threadIdx.x] = W2[threadIdx.x];
    if (threadIdx.x < D_H) sb[threadIdx.x] = b1[threadIdx.x];
    __syncthreads();

    int i = blockIdx.x * blockDim.x + threadIdx.x;
    if (i >= N_NODES) return;

    float dinv = g_dinv[i];

    const __half* ap = &g_acc1[(size_t)i * 24];
    uint4 w[3];
#pragma unroll
    for (int q = 0; q < 3; q++) w[q] = reinterpret_cast<const uint4*>(ap)[q];
    const __half2* h2v = reinterpret_cast<const __half2*>(w);

    float h1[D_H];
#pragma unroll
    for (int k = 0; k < D_H / 2; k++) {
        float2 f = __half22float2(h2v[k]);
        h1[2*k]   = gelu_exact(fmaf(dinv, f.x, sb[2*k]));
        h1[2*k+1] = gelu_exact(fmaf(dinv, f.y, sb[2*k+1]));
    }

    float h2[D_ENC];
#pragma unroll
    for (int c = 0; c < D_ENC; c++) {
        float s = 0.0f;
#pragma unroll
        for (int k = 0; k < D_H; k++) s = fmaf(h1[k], sW[k * D_ENC + c], s);
        h2[c] = s * dinv;   // pre-scaled by source dinv
    }

    __half hv[8];
#pragma unroll
    for (int k = 0; k < D_ENC; k++) hv[k] = __float2half_rn(h2[k]);
#pragma unroll
    for (int k = D_ENC; k < 8; k++) hv[k] = __float2half_rn(0.f);
    uint4 pack = *reinterpret_cast<const uint4*>(hv);
    *reinterpret_cast<uint4*>(&g_h2  [(size_t)i * 8]) = pack;
    *reinterpret_cast<uint4*>(&g_acc2[(size_t)i * 8]) = pack;
}

// layer-2 edge scatter: gather -> single v4 fp16 RED (pads are zero, adds exact)
__global__ void k_edge2(const int* __restrict__ ei) {
    int e = blockIdx.x * blockDim.x + threadIdx.x;
    if (e >= E_EDGES) return;
    int s = __ldcs(ei + e);
    int d = __ldcs(ei + E_EDGES + e);

    uint4 w = *reinterpret_cast<const uint4*>(&g_h2[(size_t)s * 8]);
    red_add_v4h2(&g_acc2[(size_t)d * 8], w.x, w.y, w.z, w.w);
}

// epilogue
__global__ void k_final(const float* __restrict__ b2,
                        const float* __restrict__ We, const float* __restrict__ be,
                        const float* __restrict__ Wd, const float* __restrict__ bd,
                        const float* __restrict__ Wr, const float* __restrict__ br,
                        float* __restrict__ out) {
    __shared__ float sWe[30 * 30];
    __shared__ float sWd[30 * 60];
    __shared__ float sWr[30 * 7];
    __shared__ float sbe[30], sbd[60], sbr[7], sb2[5];

    for (int t = threadIdx.x; t < 900;  t += blockDim.x) sWe[t] = We[t];
    for (int t = threadIdx.x; t < 1800; t += blockDim.x) sWd[t] = Wd[t];
    for (int t = threadIdx.x; t < 210;  t += blockDim.x) sWr[t] = Wr[t];
    if (threadIdx.x < 30) sbe[threadIdx.x] = be[threadIdx.x];
    if (threadIdx.x < 60) sbd[threadIdx.x] = bd[threadIdx.x];
    if (threadIdx.x < 7)  sbr[threadIdx.x] = br[threadIdx.x];
    if (threadIdx.x < 5)  sb2[threadIdx.x] = b2[threadIdx.x];
    __syncthreads();

    int b = blockIdx.x * blockDim.x + threadIdx.x;
    if (b >= B_ROWS) return;

    float r[30];
#pragma unroll
    for (int v = 0; v < VEC; v++) {
        int node = b * VEC + v;
        float dinv = g_dinv[node];
        uint4 w = *reinterpret_cast<const uint4*>(&g_acc2[(size_t)node * 8]);
        const __half* hv = reinterpret_cast<const __half*>(&w);
#pragma unroll
        for (int k = 0; k < D_ENC; k++)
            r[v * D_ENC + k] = gelu_exact(fmaf(dinv, __half2float(hv[k]), sb2[k]));
    }

    float enc[30];
#pragma unroll
    for (int o = 0; o < 30; o++) {
        float s = sbe[o];
#pragma unroll
        for (int j = 0; j < 30; j++) s = fmaf(r[j], sWe[j * 30 + o], s);
        enc[o] = s;
    }

    float* px1 = out + (size_t)b * 7;
#pragma unroll
    for (int o = 0; o < 7; o++) {
        float s = sbr[o];
#pragma unroll
        for (int j = 0; j < 30; j++) s = fmaf(enc[j], sWr[j * 7 + o], s);
        px1[o] = s;
    }

    float* pe = out + (size_t)B_ROWS * 7 + (size_t)b * 30;
#pragma unroll
    for (int o = 0; o < 30; o++) pe[o] = enc[o];

#pragma unroll
    for (int j = 0; j < 30; j++) r[j] = gelu_exact(enc[j]);
    float* po = out + (size_t)B_ROWS * 37 + (size_t)b * 60;
#pragma unroll
    for (int o = 0; o < 60; o++) {
        float s = sbd[o];
#pragma unroll
        for (int j = 0; j < 30; j++) s = fmaf(r[j], sWd[j * 60 + o], s);
        po[o] = s;
    }
}

// ---------------------------------------------------------------- launch

extern "C" void kernel_launch(void* const* d_in, const int* in_sizes, int n_in,
                              void* d_out, int out_size) {
    const float* x  = (const float*)d_in[0];
    const int*   ei = (const int*)  d_in[1];
    const float* W1 = (const float*)d_in[2];
    const float* b1 = (const float*)d_in[3];
    const float* W2 = (const float*)d_in[4];
    const float* b2 = (const float*)d_in[5];
    const float* We = (const float*)d_in[6];
    const float* be = (const float*)d_in[7];
    const float* Wd = (const float*)d_in[8];
    const float* bd = (const float*)d_in[9];
    const float* Wr = (const float*)d_in[10];
    const float* br = (const float*)d_in[11];
    float* out = (float*)d_out;

    static float* deg_ptr = nullptr;
    if (!deg_ptr) cudaGetSymbolAddress((void**)&deg_ptr, g_deg);

    const int TB = 256;
    int gN  = (N_NODES + TB - 1) / TB;
    int gE  = (E_EDGES + TB - 1) / TB;
    int gE4 = (E_EDGES / 4 + TB - 1) / TB;
    int gB  = (B_ROWS + TB - 1) / TB;

    cudaMemsetAsync(deg_ptr, 0, N_NODES * sizeof(float));
    k_deg4<<<gE4, TB>>>(ei);
    k_node1<<<gN, TB>>>(x, W1);
    k_edge1<<<gE, TB>>>(ei);
    k_node2<<<gN, TB>>>(b1, W2);
    k_edge2<<<gE, TB>>>(ei);
    k_final<<<gB, TB>>>(b2, We, be, Wd, bd, Wr, br, out);
}

// round 11
// speedup vs baseline: 1.6487x; 1.1847x over previous
#include <cuda_runtime.h>
#include <cuda_fp16.h>
#include <cuda_bf16.h>

#define N_NODES 1200000
#define E_EDGES 12000000
#define D_IN    10
#define D_H     20
#define D_ENC   5
#define VEC     6
#define B_ROWS  200000

// ---- scratch (device globals; allocation-free) ----
__device__ float  g_deg [N_NODES];
__device__ float  g_dinv[N_NODES];
// layer-1 gather source: (x+po)*dinv, fp16, 12-half rows (24B, 8B-aligned; 2 pad)
__device__ __half g_x1  [N_NODES * 12];
// layer-1 accumulator: fp16, 16-half rows (32B, 16B-aligned; v4 @0, v2 @8)
__device__ __half g_acc1[N_NODES * 16];
// layer-2 gather source: h2*dinv, fp16, 8-half rows (16B, halfs 5-7 zero)
__device__ __half g_h2  [N_NODES * 8];
// layer-2 accumulator: fp16, 8-half rows (16B) -> one v4 RED
__device__ __half g_acc2[N_NODES * 8];

__device__ __forceinline__ float gelu_exact(float v) { return v * normcdff(v); }

__device__ __forceinline__ void red_add_v4h2(__half* p, unsigned a, unsigned b,
                                             unsigned c, unsigned d) {
    asm volatile("red.global.add.noftz.v4.f16x2 [%0], {%1,%2,%3,%4};"
                 :: "l"(p), "r"(a), "r"(b), "r"(c), "r"(d) : "memory");
}
__device__ __forceinline__ void red_add_v2h2(__half* p, unsigned a, unsigned b) {
    asm volatile("red.global.add.noftz.v2.f16x2 [%0], {%1,%2};"
                 :: "l"(p), "r"(a), "r"(b) : "memory");
}

// ---------------------------------------------------------------- kernels

// degree histogram: 4 edges per thread via one int4 streaming load
__global__ void k_deg4(const int* __restrict__ ei) {
    int t = blockIdx.x * blockDim.x + threadIdx.x;
    int base = t * 4;
    if (base + 3 < E_EDGES) {
        int4 d4 = __ldcs(reinterpret_cast<const int4*>(ei + E_EDGES + base));
        atomicAdd(&g_deg[d4.x], 1.0f);
        atomicAdd(&g_deg[d4.y], 1.0f);
        atomicAdd(&g_deg[d4.z], 1.0f);
        atomicAdd(&g_deg[d4.w], 1.0f);
    } else {
        for (int e = base; e < E_EDGES; e++)
            atomicAdd(&g_deg[__ldcs(ei + E_EDGES + e)], 1.0f);
    }
}

// dinv; write fp16 (x+po)*dinv gather row + acc init (self term). No matmul.
__global__ void k_node1(const float* __restrict__ x) {
    int i = blockIdx.x * blockDim.x + threadIdx.x;
    if (i >= N_NODES) return;

    float dinv = rsqrtf(g_deg[i] + 1.0f);
    g_dinv[i] = dinv;

    __half hv[12];
#pragma unroll
    for (int j = 0; j < D_IN; j++) {
        float v = (__ldcs(x + (size_t)i * D_IN + j) + sinf((float)j)) * dinv;
        hv[j] = __float2half_rn(v);
    }
    hv[10] = __float2half_rn(0.f);
    hv[11] = __float2half_rn(0.f);

    // gather source: 24B row (stride 12 halfs, 8B-aligned) -> 3x uint2
    __half* hp = &g_x1[(size_t)i * 12];
    const uint2* src2 = reinterpret_cast<const uint2*>(hv);
#pragma unroll
    for (int q = 0; q < 3; q++) reinterpret_cast<uint2*>(hp)[q] = src2[q];

    // acc init: 32B row (stride 16 halfs, 16B-aligned): uint4 @0, uint2 @8
    __half* ap = &g_acc1[(size_t)i * 16];
    *reinterpret_cast<uint4*>(ap)     = *reinterpret_cast<const uint4*>(hv);
    *reinterpret_cast<uint2*>(ap + 8) = src2[2];
}

// layer-1 edge scatter: gather 24B -> 2 fp16 REDs (v4 + v2)
__global__ void k_edge1(const int* __restrict__ ei) {
    int e = blockIdx.x * blockDim.x + threadIdx.x;
    if (e >= E_EDGES) return;
    int s = __ldcs(ei + e);
    int d = __ldcs(ei + E_EDGES + e);

    const __half* hp = &g_x1[(size_t)s * 12];
    uint2 a0 = reinterpret_cast<const uint2*>(hp)[0];
    uint2 a1 = reinterpret_cast<const uint2*>(hp)[1];
    uint2 a2 = reinterpret_cast<const uint2*>(hp)[2];

    __half* ad = &g_acc1[(size_t)d * 16];
    red_add_v4h2(ad,     a0.x, a0.y, a1.x, a1.y);
    red_add_v2h2(ad + 8, a2.x, a2.y);
}

// t = acc1 (10-dim); h1 = gelu(dinv*(t@W1) + b1); h2 = (h1@W2)*dinv; write h2+acc2
__global__ void k_node2(const float* __restrict__ W1, const float* __restrict__ b1,
                        const float* __restrict__ W2) {
    __shared__ float sW1[D_IN * D_H];   // 200
    __shared__ float sW2[D_H * D_ENC];  // 100
    __shared__ float sb[D_H];
    if (threadIdx.x < D_IN * D_H) sW1[threadIdx.x] = W1[threadIdx.x];
    if (threadIdx.x < D_H * D_ENC) sW2[threadIdx.x] = W2[threadIdx.x];
    if (threadIdx.x < D_H) sb[threadIdx.x] = b1[threadIdx.x];
    __syncthreads();

    int i = blockIdx.x * blockDim.x + threadIdx.x;
    if (i >= N_NODES) return;

    float dinv = g_dinv[i];

    const __half* ap = &g_acc1[(size_t)i * 16];
    uint4 wa = *reinterpret_cast<const uint4*>(ap);
    uint2 wb = *reinterpret_cast<const uint2*>(ap + 8);
    __half2 h2v[6];
    *reinterpret_cast<uint4*>(&h2v[0]) = wa;
    *reinterpret_cast<uint2*>(&h2v[4]) = wb;

    float t[D_IN];
#pragma unroll
    for (int k = 0; k < 5; k++) {
        float2 f = __half22float2(h2v[k]);
        t[2*k] = f.x; t[2*k+1] = f.y;
    }

    float h1[D_H];
#pragma unroll
    for (int k = 0; k < D_H; k++) {
        float s = 0.0f;
#pragma unroll
        for (int j = 0; j < D_IN; j++) s = fmaf(t[j], sW1[j * D_H + k], s);
        h1[k] = gelu_exact(fmaf(dinv, s, sb[k]));
    }

    float h2[D_ENC];
#pragma unroll
    for (int c = 0; c < D_ENC; c++) {
        float s = 0.0f;
#pragma unroll
        for (int k = 0; k < D_H; k++) s = fmaf(h1[k], sW2[k * D_ENC + c], s);
        h2[c] = s * dinv;   // pre-scaled by source dinv
    }

    __half hv[8];
#pragma unroll
    for (int k = 0; k < D_ENC; k++) hv[k] = __float2half_rn(h2[k]);
#pragma unroll
    for (int k = D_ENC; k < 8; k++) hv[k] = __float2half_rn(0.f);
    uint4 pack = *reinterpret_cast<const uint4*>(hv);
    *reinterpret_cast<uint4*>(&g_h2  [(size_t)i * 8]) = pack;
    *reinterpret_cast<uint4*>(&g_acc2[(size_t)i * 8]) = pack;
}

// layer-2 edge scatter: gather -> single v4 fp16 RED (pads are zero, adds exact)
__global__ void k_edge2(const int* __restrict__ ei) {
    int e = blockIdx.x * blockDim.x + threadIdx.x;
    if (e >= E_EDGES) return;
    int s = __ldcs(ei + e);
    int d = __ldcs(ei + E_EDGES + e);

    uint4 w = *reinterpret_cast<const uint4*>(&g_h2[(size_t)s * 8]);
    red_add_v4h2(&g_acc2[(size_t)d * 8], w.x, w.y, w.z, w.w);
}

// epilogue
__global__ void k_final(const float* __restrict__ b2,
                        const float* __restrict__ We, const float* __restrict__ be,
                        const float* __restrict__ Wd, const float* __restrict__ bd,
                        const float* __restrict__ Wr, const float* __restrict__ br,
                        float* __restrict__ out) {
    __shared__ float sWe[30 * 30];
    __shared__ float sWd[30 * 60];
    __shared__ float sWr[30 * 7];
    __shared__ float sbe[30], sbd[60], sbr[7], sb2[5];

    for (int t = threadIdx.x; t < 900;  t += blockDim.x) sWe[t] = We[t];
    for (int t = threadIdx.x; t < 1800; t += blockDim.x) sWd[t] = Wd[t];
    for (int t = threadIdx.x; t < 210;  t += blockDim.x) sWr[t] = Wr[t];
    if (threadIdx.x < 30) sbe[threadIdx.x] = be[threadIdx.x];
    if (threadIdx.x < 60) sbd[threadIdx.x] = bd[threadIdx.x];
    if (threadIdx.x < 7)  sbr[threadIdx.x] = br[threadIdx.x];
    if (threadIdx.x < 5)  sb2[threadIdx.x] = b2[threadIdx.x];
    __syncthreads();

    int b = blockIdx.x * blockDim.x + threadIdx.x;
    if (b >= B_ROWS) return;

    float r[30];
#pragma unroll
    for (int v = 0; v < VEC; v++) {
        int node = b * VEC + v;
        float dinv = g_dinv[node];
        uint4 w = *reinterpret_cast<const uint4*>(&g_acc2[(size_t)node * 8]);
        const __half* hv = reinterpret_cast<const __half*>(&w);
#pragma unroll
        for (int k = 0; k < D_ENC; k++)
            r[v * D_ENC + k] = gelu_exact(fmaf(dinv, __half2float(hv[k]), sb2[k]));
    }

    float enc[30];
#pragma unroll
    for (int o = 0; o < 30; o++) {
        float s = sbe[o];
#pragma unroll
        for (int j = 0; j < 30; j++) s = fmaf(r[j], sWe[j * 30 + o], s);
        enc[o] = s;
    }

    float* px1 = out + (size_t)b * 7;
#pragma unroll
    for (int o = 0; o < 7; o++) {
        float s = sbr[o];
#pragma unroll
        for (int j = 0; j < 30; j++) s = fmaf(enc[j], sWr[j * 7 + o], s);
        px1[o] = s;
    }

    float* pe = out + (size_t)B_ROWS * 7 + (size_t)b * 30;
#pragma unroll
    for (int o = 0; o < 30; o++) pe[o] = enc[o];

#pragma unroll
    for (int j = 0; j < 30; j++) r[j] = gelu_exact(enc[j]);
    float* po = out + (size_t)B_ROWS * 37 + (size_t)b * 60;
#pragma unroll
    for (int o = 0; o < 60; o++) {
        float s = sbd[o];
#pragma unroll
        for (int j = 0; j < 30; j++) s = fmaf(r[j], sWd[j * 60 + o], s);
        po[o] = s;
    }
}

// ---------------------------------------------------------------- launch

extern "C" void kernel_launch(void* const* d_in, const int* in_sizes, int n_in,
                              void* d_out, int out_size) {
    const float* x  = (const float*)d_in[0];
    const int*   ei = (const int*)  d_in[1];
    const float* W1 = (const float*)d_in[2];
    const float* b1 = (const float*)d_in[3];
    const float* W2 = (const float*)d_in[4];
    const float* b2 = (const float*)d_in[5];
    const float* We = (const float*)d_in[6];
    const float* be = (const float*)d_in[7];
    const float* Wd = (const float*)d_in[8];
    const float* bd = (const float*)d_in[9];
    const float* Wr = (const float*)d_in[10];
    const float* br = (const float*)d_in[11];
    float* out = (float*)d_out;

    static float* deg_ptr = nullptr;
    if (!deg_ptr) cudaGetSymbolAddress((void**)&deg_ptr, g_deg);

    const int TB = 256;
    int gN  = (N_NODES + TB - 1) / TB;
    int gE  = (E_EDGES + TB - 1) / TB;
    int gE4 = (E_EDGES / 4 + TB - 1) / TB;
    int gB  = (B_ROWS + TB - 1) / TB;

    cudaMemsetAsync(deg_ptr, 0, N_NODES * sizeof(float));
    k_deg4<<<gE4, TB>>>(ei);
    k_node1<<<gN, TB>>>(x);
    k_edge1<<<gE, TB>>>(ei);
    k_node2<<<gN, TB>>>(W1, b1, W2);
    k_edge2<<<gE, TB>>>(ei);
    k_final<<<gB, TB>>>(b2, We, be, Wd, bd, Wr, br, out);
}

// round 12
// speedup vs baseline: 1.8313x; 1.1108x over previous
#include <cuda_runtime.h>
#include <cuda_fp16.h>
#include <cuda_bf16.h>

#define N_NODES 1200000
#define E_EDGES 12000000
#define D_IN    10
#define D_H     20
#define D_ENC   5
#define VEC     6
#define B_ROWS  200000

// ---- scratch (device globals; allocation-free) ----
__device__ float  g_deg [N_NODES];
__device__ float  g_dinv[N_NODES];
// layer-1 gather source: (x+po)*dinv, fp16, 16-half rows (32B, 32B-aligned -> 1 sector)
__device__ __half g_x1  [N_NODES * 16];
// layer-1 accumulator: fp16, 16-half rows (32B; v4 RED @0, v2 RED @8)
__device__ __half g_acc1[N_NODES * 16];
// layer-2 gather source: h2*dinv, fp16, 8-half rows (16B, halfs 5-7 zero)
__device__ __half g_h2  [N_NODES * 8];
// layer-2 accumulator: fp16, 8-half rows (16B) -> one v4 RED
__device__ __half g_acc2[N_NODES * 8];

// exact gelu via erff (identical to x*Phi(x), far cheaper than normcdff/erfcf)
__device__ __forceinline__ float gelu_exact(float v) {
    return 0.5f * v * (1.0f + erff(v * 0.7071067811865476f));
}

__device__ __forceinline__ void red_add_v4h2(__half* p, unsigned a, unsigned b,
                                             unsigned c, unsigned d) {
    asm volatile("red.global.add.noftz.v4.f16x2 [%0], {%1,%2,%3,%4};"
                 :: "l"(p), "r"(a), "r"(b), "r"(c), "r"(d) : "memory");
}
__device__ __forceinline__ void red_add_v2h2(__half* p, unsigned a, unsigned b) {
    asm volatile("red.global.add.noftz.v2.f16x2 [%0], {%1,%2};"
                 :: "l"(p), "r"(a), "r"(b) : "memory");
}

// ---------------------------------------------------------------- kernels

// degree histogram: 4 edges per thread via one int4 streaming load
__global__ void k_deg4(const int* __restrict__ ei) {
    int t = blockIdx.x * blockDim.x + threadIdx.x;
    int base = t * 4;
    if (base + 3 < E_EDGES) {
        int4 d4 = __ldcs(reinterpret_cast<const int4*>(ei + E_EDGES + base));
        atomicAdd(&g_deg[d4.x], 1.0f);
        atomicAdd(&g_deg[d4.y], 1.0f);
        atomicAdd(&g_deg[d4.z], 1.0f);
        atomicAdd(&g_deg[d4.w], 1.0f);
    } else {
        for (int e = base; e < E_EDGES; e++)
            atomicAdd(&g_deg[__ldcs(ei + E_EDGES + e)], 1.0f);
    }
}

// dinv; write fp16 (x+po)*dinv gather row (32B padded) + acc init (self term)
__global__ void k_node1(const float* __restrict__ x) {
    int i = blockIdx.x * blockDim.x + threadIdx.x;
    if (i >= N_NODES) return;

    float dinv = rsqrtf(g_deg[i] + 1.0f);
    g_dinv[i] = dinv;

    __half hv[16];
#pragma unroll
    for (int j = 0; j < D_IN; j++) {
        float v = (__ldcs(x + (size_t)i * D_IN + j) + sinf((float)j)) * dinv;
        hv[j] = __float2half_rn(v);
    }
#pragma unroll
    for (int j = D_IN; j < 16; j++) hv[j] = __float2half_rn(0.f);

    const uint4* src4 = reinterpret_cast<const uint4*>(hv);

    // gather source: 32B aligned row -> 2x uint4
    __half* hp = &g_x1[(size_t)i * 16];
    reinterpret_cast<uint4*>(hp)[0] = src4[0];
    reinterpret_cast<uint4*>(hp)[1] = src4[1];

    // acc init: 32B row: uint4 @0 + uint2 @8 (pads zero)
    __half* ap = &g_acc1[(size_t)i * 16];
    *reinterpret_cast<uint4*>(ap)     = src4[0];
    *reinterpret_cast<uint2*>(ap + 8) = reinterpret_cast<const uint2*>(hv)[2];
}

// layer-1 edge scatter: 1-sector gather -> 2 fp16 REDs (v4 + v2)
__global__ void k_edge1(const int* __restrict__ ei) {
    int e = blockIdx.x * blockDim.x + threadIdx.x;
    if (e >= E_EDGES) return;
    int s = __ldcs(ei + e);
    int d = __ldcs(ei + E_EDGES + e);

    const __half* hp = &g_x1[(size_t)s * 16];
    uint4 a0 = reinterpret_cast<const uint4*>(hp)[0];
    uint2 a1 = *reinterpret_cast<const uint2*>(hp + 8);

    __half* ad = &g_acc1[(size_t)d * 16];
    red_add_v4h2(ad,     a0.x, a0.y, a0.z, a0.w);
    red_add_v2h2(ad + 8, a1.x, a1.y);
}

// t = acc1 (10-dim); h1 = gelu(dinv*(t@W1) + b1); h2 = (h1@W2)*dinv; write h2+acc2
__global__ void k_node2(const float* __restrict__ W1, const float* __restrict__ b1,
                        const float* __restrict__ W2) {
    __shared__ float sW1[D_IN * D_H];   // 200
    __shared__ float sW2[D_H * D_ENC];  // 100
    __shared__ float sb[D_H];
    if (threadIdx.x < D_IN * D_H) sW1[threadIdx.x] = W1[threadIdx.x];
    if (threadIdx.x < D_H * D_ENC) sW2[threadIdx.x] = W2[threadIdx.x];
    if (threadIdx.x < D_H) sb[threadIdx.x] = b1[threadIdx.x];
    __syncthreads();

    int i = blockIdx.x * blockDim.x + threadIdx.x;
    if (i >= N_NODES) return;

    float dinv = g_dinv[i];

    const __half* ap = &g_acc1[(size_t)i * 16];
    uint4 wa = *reinterpret_cast<const uint4*>(ap);
    uint2 wb = *reinterpret_cast<const uint2*>(ap + 8);
    __half2 h2v[6];
    *reinterpret_cast<uint4*>(&h2v[0]) = wa;
    *reinterpret_cast<uint2*>(&h2v[4]) = wb;

    float t[D_IN];
#pragma unroll
    for (int k = 0; k < 5; k++) {
        float2 f = __half22float2(h2v[k]);
        t[2*k] = f.x; t[2*k+1] = f.y;
    }

    float h1[D_H];
#pragma unroll
    for (int k = 0; k < D_H; k++) {
        float s = 0.0f;
#pragma unroll
        for (int j = 0; j < D_IN; j++) s = fmaf(t[j], sW1[j * D_H + k], s);
        h1[k] = gelu_exact(fmaf(dinv, s, sb[k]));
    }

    float h2[D_ENC];
#pragma unroll
    for (int c = 0; c < D_ENC; c++) {
        float s = 0.0f;
#pragma unroll
        for (int k = 0; k < D_H; k++) s = fmaf(h1[k], sW2[k * D_ENC + c], s);
        h2[c] = s * dinv;   // pre-scaled by source dinv
    }

    __half hv[8];
#pragma unroll
    for (int k = 0; k < D_ENC; k++) hv[k] = __float2half_rn(h2[k]);
#pragma unroll
    for (int k = D_ENC; k < 8; k++) hv[k] = __float2half_rn(0.f);
    uint4 pack = *reinterpret_cast<const uint4*>(hv);
    *reinterpret_cast<uint4*>(&g_h2  [(size_t)i * 8]) = pack;
    *reinterpret_cast<uint4*>(&g_acc2[(size_t)i * 8]) = pack;
}

// layer-2 edge scatter: gather -> single v4 fp16 RED (pads are zero, adds exact)
__global__ void k_edge2(const int* __restrict__ ei) {
    int e = blockIdx.x * blockDim.x + threadIdx.x;
    if (e >= E_EDGES) return;
    int s = __ldcs(ei + e);
    int d = __ldcs(ei + E_EDGES + e);

    uint4 w = *reinterpret_cast<const uint4*>(&g_h2[(size_t)s * 8]);
    red_add_v4h2(&g_acc2[(size_t)d * 8], w.x, w.y, w.z, w.w);
}

// epilogue
__global__ void k_final(const float* __restrict__ b2,
                        const float* __restrict__ We, const float* __restrict__ be,
                        const float* __restrict__ Wd, const float* __restrict__ bd,
                        const float* __restrict__ Wr, const float* __restrict__ br,
                        float* __restrict__ out) {
    __shared__ float sWe[30 * 30];
    __shared__ float sWd[30 * 60];
    __shared__ float sWr[30 * 7];
    __shared__ float sbe[30], sbd[60], sbr[7], sb2[5];

    for (int t = threadIdx.x; t < 900;  t += blockDim.x) sWe[t] = We[t];
    for (int t = threadIdx.x; t < 1800; t += blockDim.x) sWd[t] = Wd[t];
    for (int t = threadIdx.x; t < 210;  t += blockDim.x) sWr[t] = Wr[t];
    if (threadIdx.x < 30) sbe[threadIdx.x] = be[threadIdx.x];
    if (threadIdx.x < 60) sbd[threadIdx.x] = bd[threadIdx.x];
    if (threadIdx.x < 7)  sbr[threadIdx.x] = br[threadIdx.x];
    if (threadIdx.x < 5)  sb2[threadIdx.x] = b2[threadIdx.x];
    __syncthreads();

    int b = blockIdx.x * blockDim.x + threadIdx.x;
    if (b >= B_ROWS) return;

    float r[30];
#pragma unroll
    for (int v = 0; v < VEC; v++) {
        int node = b * VEC + v;
        float dinv = g_dinv[node];
        uint4 w = *reinterpret_cast<const uint4*>(&g_acc2[(size_t)node * 8]);
        const __half* hv = reinterpret_cast<const __half*>(&w);
#pragma unroll
        for (int k = 0; k < D_ENC; k++)
            r[v * D_ENC + k] = gelu_exact(fmaf(dinv, __half2float(hv[k]), sb2[k]));
    }

    float enc[30];
#pragma unroll
    for (int o = 0; o < 30; o++) {
        float s = sbe[o];
#pragma unroll
        for (int j = 0; j < 30; j++) s = fmaf(r[j], sWe[j * 30 + o], s);
        enc[o] = s;
    }

    float* px1 = out + (size_t)b * 7;
#pragma unroll
    for (int o = 0; o < 7; o++) {
        float s = sbr[o];
#pragma unroll
        for (int j = 0; j < 30; j++) s = fmaf(enc[j], sWr[j * 7 + o], s);
        px1[o] = s;
    }

    float* pe = out + (size_t)B_ROWS * 7 + (size_t)b * 30;
#pragma unroll
    for (int o = 0; o < 30; o++) pe[o] = enc[o];

#pragma unroll
    for (int j = 0; j < 30; j++) r[j] = gelu_exact(enc[j]);
    float* po = out + (size_t)B_ROWS * 37 + (size_t)b * 60;
#pragma unroll
    for (int o = 0; o < 60; o++) {
        float s = sbd[o];
#pragma unroll
        for (int j = 0; j < 30; j++) s = fmaf(r[j], sWd[j * 60 + o], s);
        po[o] = s;
    }
}

// ---------------------------------------------------------------- launch

extern "C" void kernel_launch(void* const* d_in, const int* in_sizes, int n_in,
                              void* d_out, int out_size) {
    const float* x  = (const float*)d_in[0];
    const int*   ei = (const int*)  d_in[1];
    const float* W1 = (const float*)d_in[2];
    const float* b1 = (const float*)d_in[3];
    const float* W2 = (const float*)d_in[4];
    const float* b2 = (const float*)d_in[5];
    const float* We = (const float*)d_in[6];
    const float* be = (const float*)d_in[7];
    const float* Wd = (const float*)d_in[8];
    const float* bd = (const float*)d_in[9];
    const float* Wr = (const float*)d_in[10];
    const float* br = (const float*)d_in[11];
    float* out = (float*)d_out;

    static float* deg_ptr = nullptr;
    if (!deg_ptr) cudaGetSymbolAddress((void**)&deg_ptr, g_deg);

    const int TB = 256;
    int gN  = (N_NODES + TB - 1) / TB;
    int gE  = (E_EDGES + TB - 1) / TB;
    int gE4 = (E_EDGES / 4 + TB - 1) / TB;
    int gB  = (B_ROWS + TB - 1) / TB;

    cudaMemsetAsync(deg_ptr, 0, N_NODES * sizeof(float));
    k_deg4<<<gE4, TB>>>(ei);
    k_node1<<<gN, TB>>>(x);
    k_edge1<<<gE, TB>>>(ei);
    k_node2<<<gN, TB>>>(W1, b1, W2);
    k_edge2<<<gE, TB>>>(ei);
    k_final<<<gB, TB>>>(b2, We, be, Wd, bd, Wr, br, out);
}